// round 7
// baseline (speedup 1.0000x reference)
#include <cuda_runtime.h>
#include <cstdint>

#define BB 4
#define HH 8
#define SS 2048
#define DD 512
#define DH 64
#define TOPK 10

// Scratch: Q,K transposed [bh][d][s] (d-major for attn GEMM staging);
// V row-major [bh][s][d] (context reads rows).
__device__ float g_Qt[BB*HH*DH*SS];
__device__ float g_Kt[BB*HH*DH*SS];
__device__ float g_V [BB*HH*SS*DH];

__device__ __forceinline__ float neg_inf() { return __int_as_float(0xff800000); }

// ---------------------------------------------------------------------------
// Kernel 1: Y = x @ W^T + b; Q,K stored transposed via smem bounce
// (coalesced STG.128), V row-major direct. Serial ascending-k FMA chain per
// output (bit-exact, matches reference).
// ---------------------------------------------------------------------------
__global__ __launch_bounds__(256) void qkv_kernel(
    const float* __restrict__ x,
    const float* __restrict__ Wq, const float* __restrict__ bq,
    const float* __restrict__ Wk, const float* __restrict__ bk,
    const float* __restrict__ Wv, const float* __restrict__ bv)
{
    const int which = blockIdx.z;
    const float* __restrict__ W    = (which == 0) ? Wq : (which == 1) ? Wk : Wv;
    const float* __restrict__ bias = (which == 0) ? bq : (which == 1) ? bk : bv;

    __shared__ float As[16][68];   // [k][m], padded
    __shared__ float Bs[16][68];   // [k][n], padded
    __shared__ float Ts[64 * 68];  // transpose bounce [m][n]

    const int tid = threadIdx.x;
    const int tx  = tid & 15;       // 0..15 -> n
    const int ty  = tid >> 4;       // 0..15 -> m
    const int m0  = blockIdx.y * 64;
    const int n0  = blockIdx.x * 64;   // one head per n-tile (DH==64)

    const int lrow = tid >> 2;      // 0..63
    const int lk4  = tid & 3;       // 0..3

    float c[4][4];
    #pragma unroll
    for (int i = 0; i < 4; ++i)
        #pragma unroll
        for (int j = 0; j < 4; ++j) c[i][j] = 0.f;

    for (int kt = 0; kt < DD / 16; ++kt) {
        float4 av = *(const float4*)&x[(size_t)(m0 + lrow) * DD + kt * 16 + lk4 * 4];
        float4 bv4 = *(const float4*)&W[(size_t)(n0 + lrow) * DD + kt * 16 + lk4 * 4];
        __syncthreads();
        As[lk4 * 4 + 0][lrow] = av.x;
        As[lk4 * 4 + 1][lrow] = av.y;
        As[lk4 * 4 + 2][lrow] = av.z;
        As[lk4 * 4 + 3][lrow] = av.w;
        Bs[lk4 * 4 + 0][lrow] = bv4.x;
        Bs[lk4 * 4 + 1][lrow] = bv4.y;
        Bs[lk4 * 4 + 2][lrow] = bv4.z;
        Bs[lk4 * 4 + 3][lrow] = bv4.w;
        __syncthreads();
        // k ascending; each c[i][j] is one serial FMA chain over all 512 k.
        #pragma unroll
        for (int k = 0; k < 16; ++k) {
            float4 a  = *(const float4*)&As[k][ty * 4];
            float4 b4 = *(const float4*)&Bs[k][tx * 4];
            c[0][0] = fmaf(a.x, b4.x, c[0][0]); c[0][1] = fmaf(a.x, b4.y, c[0][1]);
            c[0][2] = fmaf(a.x, b4.z, c[0][2]); c[0][3] = fmaf(a.x, b4.w, c[0][3]);
            c[1][0] = fmaf(a.y, b4.x, c[1][0]); c[1][1] = fmaf(a.y, b4.y, c[1][1]);
            c[1][2] = fmaf(a.y, b4.z, c[1][2]); c[1][3] = fmaf(a.y, b4.w, c[1][3]);
            c[2][0] = fmaf(a.z, b4.x, c[2][0]); c[2][1] = fmaf(a.z, b4.y, c[2][1]);
            c[2][2] = fmaf(a.z, b4.z, c[2][2]); c[2][3] = fmaf(a.z, b4.w, c[2][3]);
            c[3][0] = fmaf(a.w, b4.x, c[3][0]); c[3][1] = fmaf(a.w, b4.y, c[3][1]);
            c[3][2] = fmaf(a.w, b4.z, c[3][2]); c[3][3] = fmaf(a.w, b4.w, c[3][3]);
        }
    }

    float4 biasv = *(const float4*)&bias[n0 + tx * 4];
    const int head = blockIdx.x;
    const int b_   = m0 >> 11;       // whole tile is inside one batch (2048%64==0)
    const int s0   = m0 & 2047;

    if (which == 2) {
        #pragma unroll
        for (int i = 0; i < 4; ++i) {
            float4 o;
            o.x = c[i][0] + biasv.x;
            o.y = c[i][1] + biasv.y;
            o.z = c[i][2] + biasv.z;
            o.w = c[i][3] + biasv.w;
            *(float4*)&g_V[(size_t)(((b_ * HH + head) * SS) + s0 + ty * 4 + i) * DH + tx * 4] = o;
        }
    } else {
        // Bounce through smem: Ts[m][n], then store coalesced rows of [d][s].
        #pragma unroll
        for (int i = 0; i < 4; ++i) {
            float4 o;
            o.x = c[i][0] + biasv.x;
            o.y = c[i][1] + biasv.y;
            o.z = c[i][2] + biasv.z;
            o.w = c[i][3] + biasv.w;
            *(float4*)&Ts[(ty * 4 + i) * 68 + tx * 4] = o;
        }
        __syncthreads();
        float* dst0 = (which == 0) ? g_Qt : g_Kt;
        const size_t obase = ((size_t)(b_ * HH + head) * DH) * SS + s0;
        const int dl  = tid >> 2;    // 0..63 output d row
        const int sf4 = tid & 3;     // 0..3
        #pragma unroll
        for (int e = 0; e < 4; ++e) {
            int sl = (e * 4 + sf4) * 4;   // starting s within tile
            float4 o;
            o.x = Ts[(sl + 0) * 68 + dl];
            o.y = Ts[(sl + 1) * 68 + dl];
            o.z = Ts[(sl + 2) * 68 + dl];
            o.w = Ts[(sl + 3) * 68 + dl];
            *(float4*)&dst0[obase + (size_t)dl * SS + sl] = o;
        }
    }
}

// ---------------------------------------------------------------------------
// Kernel 2: per (b,h, 64-q-row tile). 256 threads; each computes a 4q x 8k
// sub-tile of a 64q x 128k score tile; per d-step 3 LDS.128 -> 32 FMA.
// d-loop strictly serial ascending per accumulator (bit-exact chain).
// Zero-fills its own out_attn rows at start (replaces the memset).
// Scores dumped to smem per tile; scan (4 thr/row, interleaved col groups)
// keeps per-thread top-10; merge 4 lists/row; softmax; scatter; context.
// ---------------------------------------------------------------------------
__global__ __launch_bounds__(256, 2) void attn_kernel(
    float* __restrict__ out_ctx, float* __restrict__ out_attn)
{
    extern __shared__ float sm[];
    float* As = sm;                  // 64 x 68  [d][q]     (4352 floats)
    float* Bs = sm + 4352;           // 64 x 128 [d][k]     (8192 floats)
    float* Sc = sm + 12544;          // 64 x 144 [q][k]     (9216 floats)
    // Post-loop overlay on As/Bs region:
    float* cv = sm;                  // 256*10
    int*   ci = (int*)(sm + 2560);   // 256*10
    float* pb = sm + 5120;           // 64*10
    int*  tix = (int*)(sm + 5760);   // 64*10

    const int qt  = blockIdx.x;      // 0..31 (64 q-rows each)
    const int bh  = blockIdx.y;      // 0..31
    const int tid = threadIdx.x;     // 0..255
    const int ty  = tid >> 4;        // 0..15 -> q rows ty*4..+3
    const int tx  = tid & 15;        // 0..15 -> k cols tx*8..+7
    const int srow = tid >> 2;       // 0..63 scan row
    const int scg  = tid & 3;        // 0..3  scan col group (interleaved)

    const float* __restrict__ Qt = g_Qt + (size_t)bh * DH * SS;
    const float* __restrict__ Kt = g_Kt + (size_t)bh * DH * SS;
    const float* __restrict__ Vb = g_V  + (size_t)bh * SS * DH;

    // Phase 0: zero this block's 64 attn rows (replaces global memset;
    // overlaps GEMM compute since DRAM is otherwise idle).
    {
        float4 z = make_float4(0.f, 0.f, 0.f, 0.f);
        float4* dst = (float4*)(out_attn + ((size_t)bh * SS + qt * 64) * SS);
        #pragma unroll 4
        for (int i = tid; i < 64 * (SS / 4); i += 256) dst[i] = z;
    }

    // Stage As = Q^T tile (64d x 64q), scaled by 1/8 (exact pow2).
    #pragma unroll
    for (int p = 0; p < 4; ++p) {
        int idx = p * 256 + tid;     // 0..1023 float4s
        int d   = idx >> 4;
        int qf4 = idx & 15;
        float4 v = *(const float4*)&Qt[(size_t)d * SS + qt * 64 + qf4 * 4];
        v.x *= 0.125f; v.y *= 0.125f; v.z *= 0.125f; v.w *= 0.125f;
        *(float4*)&As[d * 68 + qf4 * 4] = v;
    }

    float tv[TOPK];
    int   ti[TOPK];
    #pragma unroll
    for (int t = 0; t < TOPK; ++t) { tv[t] = neg_inf(); ti[t] = 0x7FFFFFFF; }

    for (int kt = 0; kt < SS / 128; ++kt) {
        // Stage Bs = K^T tile (64d x 128k). No hazard with previous scan
        // (scan reads Sc only); previous GEMM's Bs reads ended before the
        // dump-sync of the previous iteration.
        #pragma unroll
        for (int p = 0; p < 8; ++p) {
            int idx = p * 256 + tid; // 0..2047 float4s
            int d   = idx >> 5;
            int kf4 = idx & 31;
            *(float4*)&Bs[d * 128 + kf4 * 4] =
                *(const float4*)&Kt[(size_t)d * SS + kt * 128 + kf4 * 4];
        }
        __syncthreads();

        // GEMM: 4q x 8k accumulators, d ascending serial per accumulator.
        float a[4][8];
        #pragma unroll
        for (int i = 0; i < 4; ++i)
            #pragma unroll
            for (int j = 0; j < 8; ++j) a[i][j] = 0.f;
        #pragma unroll 8
        for (int d = 0; d < 64; ++d) {
            float4 q  = *(const float4*)&As[d * 68 + ty * 4];
            float4 k0 = *(const float4*)&Bs[d * 128 + tx * 8];
            float4 k1 = *(const float4*)&Bs[d * 128 + tx * 8 + 4];
            float qq[4] = {q.x, q.y, q.z, q.w};
            float kk[8] = {k0.x, k0.y, k0.z, k0.w, k1.x, k1.y, k1.z, k1.w};
            #pragma unroll
            for (int i = 0; i < 4; ++i)
                #pragma unroll
                for (int j = 0; j < 8; ++j)
                    a[i][j] = fmaf(qq[i], kk[j], a[i][j]);
        }
        // Dump scores to smem.
        #pragma unroll
        for (int i = 0; i < 4; ++i) {
            *(float4*)&Sc[(ty*4+i) * 144 + tx*8]     = make_float4(a[i][0], a[i][1], a[i][2], a[i][3]);
            *(float4*)&Sc[(ty*4+i) * 144 + tx*8 + 4] = make_float4(a[i][4], a[i][5], a[i][6], a[i][7]);
        }
        __syncthreads();

        // Scan: interleaved column groups (conflict-free with stride 144);
        // k ascending within thread; cross-thread ties resolved in merge.
        #pragma unroll
        for (int m = 0; m < 8; ++m) {
            float4 s = *(const float4*)&Sc[srow * 144 + m * 16 + scg * 4];
            int k0 = kt * 128 + m * 16 + scg * 4;
            float sv[4] = {s.x, s.y, s.z, s.w};
            #pragma unroll
            for (int e = 0; e < 4; ++e) {
                if (sv[e] > tv[TOPK - 1]) {
                    float vs = sv[e]; int is = k0 + e;
                    #pragma unroll
                    for (int t = 0; t < TOPK; ++t) {
                        if (vs > tv[t]) {
                            float tmpv = tv[t]; tv[t] = vs; vs = tmpv;
                            int tmpi = ti[t]; ti[t] = is; is = tmpi;
                        }
                    }
                }
            }
        }
        __syncthreads();   // scans done before next Bs stage / final overlay
    }

    // Overlay candidate lists onto As/Bs region (dead now).
    #pragma unroll
    for (int t = 0; t < TOPK; ++t) {
        cv[tid * TOPK + t] = tv[t];
        ci[tid * TOPK + t] = ti[t];
    }
    __syncthreads();

    // Merge 4 candidate lists per row; ties -> lower index (lax.top_k).
    if (tid < 64) {
        int base = tid * 4 * TOPK;
        for (int s = 0; s < TOPK; ++s) {
            float best = neg_inf(); int bi = 0x7FFFFFFF; int bp = 0;
            for (int p = 0; p < 4 * TOPK; ++p) {
                float v = cv[base + p]; int ii = ci[base + p];
                if (v > best || (v == best && ii < bi)) { best = v; bi = ii; bp = p; }
            }
            cv[base + bp] = neg_inf();
            pb[tid * TOPK + s] = best;
            tix[tid * TOPK + s] = bi;
        }
        float mx = pb[tid * TOPK];
        float pr[TOPK]; float Z = 0.f;
        #pragma unroll
        for (int s = 0; s < TOPK; ++s) {
            float e = expf(pb[tid * TOPK + s] - mx);
            pr[s] = e; Z += e;
        }
        #pragma unroll
        for (int s = 0; s < TOPK; ++s) pb[tid * TOPK + s] = pr[s] / Z;
    }
    __syncthreads();

    const int q = qt * 64 + srow;
    const size_t abase = ((size_t)bh * SS + q) * SS;
    for (int t = scg; t < TOPK; t += 4)
        out_attn[abase + tix[srow * TOPK + t]] = pb[srow * TOPK + t];

    // Context: 4 threads per row, 16 dh-columns each.
    float acc[16];
    #pragma unroll
    for (int j = 0; j < 16; ++j) acc[j] = 0.f;
    #pragma unroll
    for (int t = 0; t < TOPK; ++t) {
        float p = pb[srow * TOPK + t];
        const float* vr = &Vb[(size_t)tix[srow * TOPK + t] * DH + scg * 16];
        #pragma unroll
        for (int j4 = 0; j4 < 4; ++j4) {
            float4 v = *(const float4*)&vr[j4 * 4];
            acc[j4*4+0] = fmaf(p, v.x, acc[j4*4+0]);
            acc[j4*4+1] = fmaf(p, v.y, acc[j4*4+1]);
            acc[j4*4+2] = fmaf(p, v.z, acc[j4*4+2]);
            acc[j4*4+3] = fmaf(p, v.w, acc[j4*4+3]);
        }
    }
    const int b_ = bh >> 3, h_ = bh & 7;
    float* dst = out_ctx + ((size_t)(b_ * SS + q)) * DD + h_ * DH + scg * 16;
    #pragma unroll
    for (int j4 = 0; j4 < 4; ++j4) {
        float4 o;
        o.x = acc[j4*4+0]; o.y = acc[j4*4+1];
        o.z = acc[j4*4+2]; o.w = acc[j4*4+3];
        *(float4*)&dst[j4 * 4] = o;
    }
}

// ---------------------------------------------------------------------------
extern "C" void kernel_launch(void* const* d_in, const int* in_sizes, int n_in,
                              void* d_out, int out_size)
{
    const float* x  = (const float*)d_in[0];
    const float* Wq = (const float*)d_in[1];
    const float* bq = (const float*)d_in[2];
    const float* Wk = (const float*)d_in[3];
    const float* bk = (const float*)d_in[4];
    const float* Wv = (const float*)d_in[5];
    const float* bv = (const float*)d_in[6];

    float* out_ctx  = (float*)d_out;
    float* out_attn = out_ctx + (size_t)BB * SS * DD;

    static int smem_set = 0;
    const int attn_smem = 21760 * 4;   // As+Bs+Sc floats
    if (!smem_set) {
        cudaFuncSetAttribute(attn_kernel,
                             cudaFuncAttributeMaxDynamicSharedMemorySize, attn_smem);
        smem_set = 1;
    }

    dim3 g1(DD / 64, (BB * SS) / 64, 3);   // (8, 128, 3)
    qkv_kernel<<<g1, 256>>>(x, Wq, bq, Wk, bk, Wv, bv);

    dim3 g2(SS / 64, BB * HH);             // (32, 32)
    attn_kernel<<<g2, 256, attn_smem>>>(out_ctx, out_attn);
}

// round 8
// speedup vs baseline: 1.1062x; 1.1062x over previous
#include <cuda_runtime.h>
#include <cstdint>

#define BB 4
#define HH 8
#define SS 2048
#define DD 512
#define DH 64
#define TOPK 10

// Scratch: Q,K transposed [bh][d][s] (d-major for attn GEMM staging);
// V row-major [bh][s][d] (context reads rows).
__device__ float g_Qt[BB*HH*DH*SS];
__device__ float g_Kt[BB*HH*DH*SS];
__device__ float g_V [BB*HH*SS*DH];

__device__ __forceinline__ float neg_inf() { return __int_as_float(0xff800000); }

__device__ __forceinline__ void cpa16(void* s, const void* g) {
    uint32_t sa = (uint32_t)__cvta_generic_to_shared(s);
    asm volatile("cp.async.cg.shared.global [%0], [%1], 16;" :: "r"(sa), "l"(g));
}
__device__ __forceinline__ void cpa_commit() {
    asm volatile("cp.async.commit_group;");
}
__device__ __forceinline__ void cpa_wait0() {
    asm volatile("cp.async.wait_group 0;");
}

// ---------------------------------------------------------------------------
// Kernel 1: Y = x @ W^T + b; Q,K scattered transposed, V row-major.
// Serial ascending-k FMA chain per output (bit-exact, matches reference).
// AT the 3-reg FFMA roofline — do not touch.
// ---------------------------------------------------------------------------
__global__ __launch_bounds__(256) void qkv_kernel(
    const float* __restrict__ x,
    const float* __restrict__ Wq, const float* __restrict__ bq,
    const float* __restrict__ Wk, const float* __restrict__ bk,
    const float* __restrict__ Wv, const float* __restrict__ bv)
{
    const int which = blockIdx.z;
    const float* __restrict__ W    = (which == 0) ? Wq : (which == 1) ? Wk : Wv;
    const float* __restrict__ bias = (which == 0) ? bq : (which == 1) ? bk : bv;

    __shared__ float As[16][68];   // [k][m], padded
    __shared__ float Bs[16][68];   // [k][n], padded

    const int tid = threadIdx.x;
    const int tx  = tid & 15;       // 0..15 -> n
    const int ty  = tid >> 4;       // 0..15 -> m
    const int m0  = blockIdx.y * 64;
    const int n0  = blockIdx.x * 64;   // one head per n-tile (DH==64)

    const int lrow = tid >> 2;      // 0..63
    const int lk4  = tid & 3;       // 0..3

    float c[4][4];
    #pragma unroll
    for (int i = 0; i < 4; ++i)
        #pragma unroll
        for (int j = 0; j < 4; ++j) c[i][j] = 0.f;

    for (int kt = 0; kt < DD / 16; ++kt) {
        float4 av = *(const float4*)&x[(size_t)(m0 + lrow) * DD + kt * 16 + lk4 * 4];
        float4 bv4 = *(const float4*)&W[(size_t)(n0 + lrow) * DD + kt * 16 + lk4 * 4];
        __syncthreads();
        As[lk4 * 4 + 0][lrow] = av.x;
        As[lk4 * 4 + 1][lrow] = av.y;
        As[lk4 * 4 + 2][lrow] = av.z;
        As[lk4 * 4 + 3][lrow] = av.w;
        Bs[lk4 * 4 + 0][lrow] = bv4.x;
        Bs[lk4 * 4 + 1][lrow] = bv4.y;
        Bs[lk4 * 4 + 2][lrow] = bv4.z;
        Bs[lk4 * 4 + 3][lrow] = bv4.w;
        __syncthreads();
        // k ascending; each c[i][j] is one serial FMA chain over all 512 k.
        #pragma unroll
        for (int k = 0; k < 16; ++k) {
            float4 a  = *(const float4*)&As[k][ty * 4];
            float4 b4 = *(const float4*)&Bs[k][tx * 4];
            c[0][0] = fmaf(a.x, b4.x, c[0][0]); c[0][1] = fmaf(a.x, b4.y, c[0][1]);
            c[0][2] = fmaf(a.x, b4.z, c[0][2]); c[0][3] = fmaf(a.x, b4.w, c[0][3]);
            c[1][0] = fmaf(a.y, b4.x, c[1][0]); c[1][1] = fmaf(a.y, b4.y, c[1][1]);
            c[1][2] = fmaf(a.y, b4.z, c[1][2]); c[1][3] = fmaf(a.y, b4.w, c[1][3]);
            c[2][0] = fmaf(a.z, b4.x, c[2][0]); c[2][1] = fmaf(a.z, b4.y, c[2][1]);
            c[2][2] = fmaf(a.z, b4.z, c[2][2]); c[2][3] = fmaf(a.z, b4.w, c[2][3]);
            c[3][0] = fmaf(a.w, b4.x, c[3][0]); c[3][1] = fmaf(a.w, b4.y, c[3][1]);
            c[3][2] = fmaf(a.w, b4.z, c[3][2]); c[3][3] = fmaf(a.w, b4.w, c[3][3]);
        }
    }

    float4 biasv = *(const float4*)&bias[n0 + tx * 4];
    const int head = blockIdx.x;
    #pragma unroll
    for (int i = 0; i < 4; ++i) {
        int m  = m0 + ty * 4 + i;
        int b_ = m >> 11;        // m / 2048
        int s_ = m & 2047;
        float o0 = c[i][0] + biasv.x;
        float o1 = c[i][1] + biasv.y;
        float o2 = c[i][2] + biasv.z;
        float o3 = c[i][3] + biasv.w;
        if (which == 2) {
            float4 o; o.x = o0; o.y = o1; o.z = o2; o.w = o3;
            *(float4*)&g_V[(size_t)(((b_ * HH + head) * SS) + s_) * DH + tx * 4] = o;
        } else {
            float* dst = (which == 0) ? g_Qt : g_Kt;
            size_t base = ((size_t)(b_ * HH + head) * DH + tx * 4) * SS + s_;
            dst[base + 0 * SS] = o0;
            dst[base + 1 * SS] = o1;
            dst[base + 2 * SS] = o2;
            dst[base + 3 * SS] = o3;
        }
    }
}

// ---------------------------------------------------------------------------
// Kernel 2 (R6 structure + cp.async pipeline + smem overlay + scan fast path).
// Per (b,h, 32-q-row tile): 128 threads, each a 4q x 4k sub-tile of a
// 32q x 64k score tile; d-loop strictly serial ascending per accumulator.
// K tiles prefetched with cp.async overlapping the scan phase.
// ---------------------------------------------------------------------------
__global__ __launch_bounds__(128, 5) void attn_kernel(
    float* __restrict__ out_ctx, float* __restrict__ out_attn)
{
    __shared__ float As[64 * 36];        // Q  [d][q]
    __shared__ float Bs[64 * 68];        // K  [d][k]
    __shared__ float Sc[32 * 68];        // scores [q][k]
    // Post-loop overlays (regions dead after the last GEMM/scan):
    float* cv  = Bs;                     // 128*10 floats
    int*   ci  = (int*)(Bs + 1280);      // 128*10 ints
    float* pb  = As;                     // 32*10 floats
    int*   tix = (int*)(As + 320);       // 32*10 ints

    const int qt  = blockIdx.x;      // 0..63 (32 q-rows each)
    const int bh  = blockIdx.y;      // 0..31
    const int tid = threadIdx.x;     // 0..127
    const int ty  = tid >> 4;        // 0..7  -> q rows ty*4..+3
    const int tx  = tid & 15;        // 0..15 -> k cols tx*4..+3
    const int srow = tid >> 2;       // 0..31 scan row
    const int scg  = tid & 3;        // 0..3  scan col group

    const float* __restrict__ Qt = g_Qt + (size_t)bh * DH * SS;
    const float* __restrict__ Kt = g_Kt + (size_t)bh * DH * SS;
    const float* __restrict__ Vb = g_V  + (size_t)bh * SS * DH;

    // Stage As = Q^T tile (64d x 32q), scaled by 1/8 (exact pow2).
    #pragma unroll
    for (int p = 0; p < 4; ++p) {
        int idx = p * 128 + tid;     // 0..511 float4s
        int d   = idx >> 3;
        int qf4 = idx & 7;
        float4 v = *(const float4*)&Qt[(size_t)d * SS + qt * 32 + qf4 * 4];
        v.x *= 0.125f; v.y *= 0.125f; v.z *= 0.125f; v.w *= 0.125f;
        *(float4*)&As[d * 36 + qf4 * 4] = v;
    }

    // Preload K tile 0 via cp.async (8 float4 per thread).
    #pragma unroll
    for (int p = 0; p < 8; ++p) {
        int idx = p * 128 + tid;     // 0..1023 float4s
        int d   = idx >> 4;
        int kf4 = idx & 15;
        cpa16(&Bs[d * 68 + kf4 * 4], &Kt[(size_t)d * SS + kf4 * 4]);
    }
    cpa_commit();
    cpa_wait0();
    __syncthreads();                  // As + Bs(tile 0) ready

    float tv[TOPK];
    int   ti[TOPK];
    #pragma unroll
    for (int t = 0; t < TOPK; ++t) { tv[t] = neg_inf(); ti[t] = 0x7FFFFFFF; }

    for (int kt = 0; kt < SS / 64; ++kt) {
        // GEMM: 4x4 accumulators, d ascending serial per accumulator.
        float a0[4], a1[4], a2[4], a3[4];
        #pragma unroll
        for (int j = 0; j < 4; ++j) { a0[j]=0.f; a1[j]=0.f; a2[j]=0.f; a3[j]=0.f; }
        #pragma unroll 8
        for (int d = 0; d < 64; ++d) {
            float4 q = *(const float4*)&As[d * 36 + ty * 4];
            float4 k = *(const float4*)&Bs[d * 68 + tx * 4];
            a0[0]=fmaf(q.x,k.x,a0[0]); a0[1]=fmaf(q.x,k.y,a0[1]);
            a0[2]=fmaf(q.x,k.z,a0[2]); a0[3]=fmaf(q.x,k.w,a0[3]);
            a1[0]=fmaf(q.y,k.x,a1[0]); a1[1]=fmaf(q.y,k.y,a1[1]);
            a1[2]=fmaf(q.y,k.z,a1[2]); a1[3]=fmaf(q.y,k.w,a1[3]);
            a2[0]=fmaf(q.z,k.x,a2[0]); a2[1]=fmaf(q.z,k.y,a2[1]);
            a2[2]=fmaf(q.z,k.z,a2[2]); a2[3]=fmaf(q.z,k.w,a2[3]);
            a3[0]=fmaf(q.w,k.x,a3[0]); a3[1]=fmaf(q.w,k.y,a3[1]);
            a3[2]=fmaf(q.w,k.z,a3[2]); a3[3]=fmaf(q.w,k.w,a3[3]);
        }
        // Dump scores to smem.
        *(float4*)&Sc[(ty*4+0)*68 + tx*4] = make_float4(a0[0],a0[1],a0[2],a0[3]);
        *(float4*)&Sc[(ty*4+1)*68 + tx*4] = make_float4(a1[0],a1[1],a1[2],a1[3]);
        *(float4*)&Sc[(ty*4+2)*68 + tx*4] = make_float4(a2[0],a2[1],a2[2],a2[3]);
        *(float4*)&Sc[(ty*4+3)*68 + tx*4] = make_float4(a3[0],a3[1],a3[2],a3[3]);
        __syncthreads();             // all GEMM reads of Bs done; Sc ready

        // Prefetch next K tile into Bs — overlaps the scan below.
        if (kt + 1 < SS / 64) {
            #pragma unroll
            for (int p = 0; p < 8; ++p) {
                int idx = p * 128 + tid;
                int d   = idx >> 4;
                int kf4 = idx & 15;
                cpa16(&Bs[d * 68 + kf4 * 4],
                      &Kt[(size_t)d * SS + (kt + 1) * 64 + kf4 * 4]);
            }
            cpa_commit();
        }

        // Scan this thread's 16 columns of its row, ascending k, with a
        // max-of-4 fast path (selection semantics identical).
        #pragma unroll
        for (int j4 = 0; j4 < 4; ++j4) {
            float4 s = *(const float4*)&Sc[srow * 68 + scg * 16 + j4 * 4];
            float mx4 = fmaxf(fmaxf(s.x, s.y), fmaxf(s.z, s.w));
            if (mx4 > tv[TOPK - 1]) {
                int k0 = kt * 64 + scg * 16 + j4 * 4;
                float sv[4] = {s.x, s.y, s.z, s.w};
                #pragma unroll
                for (int e = 0; e < 4; ++e) {
                    if (sv[e] > tv[TOPK - 1]) {
                        float vs = sv[e]; int is = k0 + e;
                        #pragma unroll
                        for (int t = 0; t < TOPK; ++t) {
                            if (vs > tv[t]) {
                                float tmpv = tv[t]; tv[t] = vs; vs = tmpv;
                                int tmpi = ti[t]; ti[t] = is; is = tmpi;
                            }
                        }
                    }
                }
            }
        }
        cpa_wait0();
        __syncthreads();             // next Bs tile resident; scans done
    }

    // Candidate lists into overlay (Bs dead after final sync above).
    #pragma unroll
    for (int t = 0; t < TOPK; ++t) {
        cv[tid * TOPK + t] = tv[t];
        ci[tid * TOPK + t] = ti[t];
    }
    __syncthreads();

    // Merge 4 candidate lists per row; ties -> lower index (lax.top_k).
    if (tid < 32) {
        int base = tid * 4 * TOPK;
        for (int s = 0; s < TOPK; ++s) {
            float best = neg_inf(); int bi = 0x7FFFFFFF; int bp = 0;
            for (int p = 0; p < 4 * TOPK; ++p) {
                float v = cv[base + p]; int ii = ci[base + p];
                if (v > best || (v == best && ii < bi)) { best = v; bi = ii; bp = p; }
            }
            cv[base + bp] = neg_inf();
            pb[tid * TOPK + s] = best;
            tix[tid * TOPK + s] = bi;
        }
        float mx = pb[tid * TOPK];
        float pr[TOPK]; float Z = 0.f;
        #pragma unroll
        for (int s = 0; s < TOPK; ++s) {
            float e = expf(pb[tid * TOPK + s] - mx);
            pr[s] = e; Z += e;
        }
        #pragma unroll
        for (int s = 0; s < TOPK; ++s) pb[tid * TOPK + s] = pr[s] / Z;
    }
    __syncthreads();

    const int q = qt * 32 + srow;
    const size_t abase = ((size_t)bh * SS + q) * SS;
    for (int t = scg; t < TOPK; t += 4)
        out_attn[abase + tix[srow * TOPK + t]] = pb[srow * TOPK + t];

    // Context: 4 threads per row, 16 dh-columns each.
    float acc[16];
    #pragma unroll
    for (int j = 0; j < 16; ++j) acc[j] = 0.f;
    #pragma unroll
    for (int t = 0; t < TOPK; ++t) {
        float p = pb[srow * TOPK + t];
        const float* vr = &Vb[(size_t)tix[srow * TOPK + t] * DH + scg * 16];
        #pragma unroll
        for (int j4 = 0; j4 < 4; ++j4) {
            float4 v = *(const float4*)&vr[j4 * 4];
            acc[j4*4+0] = fmaf(p, v.x, acc[j4*4+0]);
            acc[j4*4+1] = fmaf(p, v.y, acc[j4*4+1]);
            acc[j4*4+2] = fmaf(p, v.z, acc[j4*4+2]);
            acc[j4*4+3] = fmaf(p, v.w, acc[j4*4+3]);
        }
    }
    const int b_ = bh >> 3, h_ = bh & 7;
    float* dst = out_ctx + ((size_t)(b_ * SS + q)) * DD + h_ * DH + scg * 16;
    #pragma unroll
    for (int j4 = 0; j4 < 4; ++j4) {
        float4 o;
        o.x = acc[j4*4+0]; o.y = acc[j4*4+1];
        o.z = acc[j4*4+2]; o.w = acc[j4*4+3];
        *(float4*)&dst[j4 * 4] = o;
    }
}

// ---------------------------------------------------------------------------
extern "C" void kernel_launch(void* const* d_in, const int* in_sizes, int n_in,
                              void* d_out, int out_size)
{
    const float* x  = (const float*)d_in[0];
    const float* Wq = (const float*)d_in[1];
    const float* bq = (const float*)d_in[2];
    const float* Wk = (const float*)d_in[3];
    const float* bk = (const float*)d_in[4];
    const float* Wv = (const float*)d_in[5];
    const float* bv = (const float*)d_in[6];

    float* out_ctx  = (float*)d_out;
    float* out_attn = out_ctx + (size_t)BB * SS * DD;

    // attn output is exactly 10 nonzeros/row: zero-fill then scatter.
    cudaMemsetAsync(out_attn, 0, (size_t)BB * HH * SS * SS * sizeof(float));

    dim3 g1(DD / 64, (BB * SS) / 64, 3);   // (8, 128, 3)
    qkv_kernel<<<g1, 256>>>(x, Wq, bq, Wk, bk, Wv, bv);

    dim3 g2(SS / 32, BB * HH);             // (64, 32)
    attn_kernel<<<g2, 128>>>(out_ctx, out_attn);
}